// round 1
// baseline (speedup 1.0000x reference)
#include <cuda_runtime.h>
#include <math.h>

// EmbeddingToExpression: per-region MLP 16 -> 5 (exact-erf GELU) -> 1
//   R=1024 regions, C=8192 cells, DIN=16, E=5, NREG=2048
//   out[c, r] = sum_e gelu( emb[r,c,:] . W1[oi[r],:,e] + b1[oi[r],e] ) * Wf[oi[r],e,0]
//
// HBM-bound: 512 MiB embedding read + 32 MiB transposed write.
// Block = 8 regions x 256 cells. Warp-per-region (coalesced float4 reads),
// SMEM transpose so the [C,R] output is written as 32B-contiguous float4 pairs.

#define RR    1024
#define CC    8192
#define DIN   16
#define EE    5
#define CPB   256   // cells per block
#define RPB   8     // regions per block (one warp each)

__global__ __launch_bounds__(256)
void e2e_kernel(const float* __restrict__ emb,
                const void*  __restrict__ oi,     // int32 or int64, detected
                const float* __restrict__ W1,     // [NREG, DIN, E]
                const float* __restrict__ b1,     // [NREG, E]
                const float* __restrict__ Wf,     // [NREG, E, 1]
                float* __restrict__ out)          // [C, R]
{
    __shared__ float s_out[RPB * CPB];   // [region_local][cell_local]
    __shared__ int   s_is64;

    // Detect regions_oi element width. Values are in [0, 2048): if int64
    // (little-endian), every odd 32-bit word of the first 32 elements is 0.
    // Probes only the first 256 bytes — safe for either dtype.
    if (threadIdx.x == 0) {
        const int* w = (const int*)oi;
        int all0 = 1;
        #pragma unroll
        for (int k = 0; k < 32; k++) all0 &= (w[2 * k + 1] == 0);
        s_is64 = all0;
    }
    __syncthreads();

    const int warp = threadIdx.x >> 5;
    const int lane = threadIdx.x & 31;
    const int r    = blockIdx.y * RPB + warp;   // region handled by this warp
    const int c0   = blockIdx.x * CPB;          // first cell of this block

    int reg;
    if (s_is64) reg = (int)((const long long*)oi)[r];
    else        reg = ((const int*)oi)[r];

    // ---- per-region weights into registers (broadcast loads, L2-resident) ----
    float w[DIN * EE];                          // [i*E + e]
    {
        const float4* wp = (const float4*)(W1 + (size_t)reg * (DIN * EE));
        #pragma unroll
        for (int q = 0; q < (DIN * EE) / 4; q++) {
            float4 v = wp[q];
            w[4 * q + 0] = v.x; w[4 * q + 1] = v.y;
            w[4 * q + 2] = v.z; w[4 * q + 3] = v.w;
        }
    }
    float bb[EE], wf[EE];
    #pragma unroll
    for (int e = 0; e < EE; e++) {
        bb[e] = b1[reg * EE + e];
        wf[e] = Wf[reg * EE + e];
    }

    // ---- compute: each lane handles cells lane, lane+32, ... (coalesced) ----
    const float4* ep = (const float4*)(emb + ((size_t)r * CC + c0) * DIN);

    #pragma unroll
    for (int k = 0; k < CPB / 32; k++) {
        const int cl = lane + 32 * k;
        float4 v0 = ep[cl * 4 + 0];
        float4 v1 = ep[cl * 4 + 1];
        float4 v2 = ep[cl * 4 + 2];
        float4 v3 = ep[cl * 4 + 3];
        float x[DIN] = { v0.x, v0.y, v0.z, v0.w,
                         v1.x, v1.y, v1.z, v1.w,
                         v2.x, v2.y, v2.z, v2.w,
                         v3.x, v3.y, v3.z, v3.w };

        float h[EE];
        #pragma unroll
        for (int e = 0; e < EE; e++) h[e] = bb[e];
        #pragma unroll
        for (int i = 0; i < DIN; i++) {
            #pragma unroll
            for (int e = 0; e < EE; e++)
                h[e] = fmaf(x[i], w[i * EE + e], h[e]);
        }

        float acc = 0.0f;
        #pragma unroll
        for (int e = 0; e < EE; e++) {
            float he = h[e];
            float g  = 0.5f * he * (1.0f + erff(he * 0.70710678118654752f));
            acc = fmaf(g, wf[e], acc);
        }
        s_out[warp * CPB + cl] = acc;
    }
    __syncthreads();

    // ---- transposed write: thread t owns cell c0+t, emits 8 region values
    //      as two float4 stores (32B contiguous, sector-exact: r_base % 8 == 0)
    const int c = threadIdx.x;
    float4 o0, o1;
    o0.x = s_out[0 * CPB + c];
    o0.y = s_out[1 * CPB + c];
    o0.z = s_out[2 * CPB + c];
    o0.w = s_out[3 * CPB + c];
    o1.x = s_out[4 * CPB + c];
    o1.y = s_out[5 * CPB + c];
    o1.z = s_out[6 * CPB + c];
    o1.w = s_out[7 * CPB + c];

    float* op = out + (size_t)(c0 + c) * RR + (size_t)blockIdx.y * RPB;
    ((float4*)op)[0] = o0;
    ((float4*)op)[1] = o1;
}

extern "C" void kernel_launch(void* const* d_in, const int* in_sizes, int n_in,
                              void* d_out, int out_size)
{
    const float* emb = (const float*)d_in[0];   // [R, C, DIN] f32
    const void*  oi  = d_in[1];                 // [R] int32 or int64
    const float* W1  = (const float*)d_in[2];   // [NREG, DIN, E] f32
    const float* b1  = (const float*)d_in[3];   // [NREG, E] f32
    const float* Wf  = (const float*)d_in[4];   // [NREG, E, 1] f32
    float* out = (float*)d_out;                 // [C, R] f32

    dim3 grid(CC / CPB, RR / RPB);              // (32, 128)
    e2e_kernel<<<grid, 256>>>(emb, oi, W1, b1, Wf, out);
}